// round 6
// baseline (speedup 1.0000x reference)
#include <cuda_runtime.h>
#include <cuda_bf16.h>
#include <cstdint>

// Problem constants (fixed by the dataset)
#define N_ENT   100000
#define N_REL   250000
#define N_TRIG  50000
#define N_ARGS  250000
#define ENT_DIM 288
#define REL_R   256
#define RTYPE_D 32
#define ROLE    256
#define KDIM    576          // REL_R + RTYPE_D + ENT_DIM
#define OUTW    544          // ENT_DIM + ROLE

#define TILE    64
#define NTILES  ((N_ARGS + TILE + TILE - 1) / TILE)   // 3908
#define PERM_SZ (NTILES * TILE)                        // 250112

typedef unsigned long long ull;

// Scratch (no allocations allowed -> device globals)
__device__ int g_perm[PERM_SZ];
__device__ int g_meta[4];   // [0]=n_in, [1]=c_in, [2]=c_out, [3]=unused

// ---------- packed f32x2 helpers ----------
__device__ __forceinline__ ull pk2(float lo, float hi) {
    ull r;
    asm("mov.b64 %0, {%1, %2};" : "=l"(r) : "f"(lo), "f"(hi));
    return r;
}
__device__ __forceinline__ void upk2(ull v, float& lo, float& hi) {
    asm("mov.b64 {%0, %1}, %2;" : "=f"(lo), "=f"(hi) : "l"(v));
}
__device__ __forceinline__ void ffma2(ull& d, ull a, ull b) {
    asm("fma.rn.f32x2 %0, %1, %2, %0;" : "+l"(d) : "l"(a), "l"(b));
}

// ---------- kernel 1: reset scratch ----------
__global__ void k_init() {
    int i = blockIdx.x * blockDim.x + threadIdx.x;
    for (; i < PERM_SZ; i += gridDim.x * blockDim.x) g_perm[i] = -1;
    if (blockIdx.x == 0 && threadIdx.x == 0) {
        g_meta[0] = 0; g_meta[1] = 0; g_meta[2] = 0; g_meta[3] = 0;
    }
}

// ---------- kernel 2: count in-args ----------
__global__ void k_count(const int* __restrict__ is_in) {
    int s = 0;
    for (int i = blockIdx.x * blockDim.x + threadIdx.x; i < N_ARGS;
         i += gridDim.x * blockDim.x)
        s += is_in[i];
    #pragma unroll
    for (int o = 16; o; o >>= 1) s += __shfl_down_sync(0xffffffffu, s, o);
    __shared__ int sh[8];
    if ((threadIdx.x & 31) == 0) sh[threadIdx.x >> 5] = s;
    __syncthreads();
    if (threadIdx.x < 8) {
        s = sh[threadIdx.x];
        #pragma unroll
        for (int o = 4; o; o >>= 1) s += __shfl_down_sync(0xffu, s, o);
        if (threadIdx.x == 0) atomicAdd(&g_meta[0], s);
    }
}

// ---------- kernel 3: place args (warp-aggregated) ----------
__global__ void k_place(const int* __restrict__ is_in) {
    const int i = blockIdx.x * blockDim.x + threadIdx.x;
    const int pad = (g_meta[0] + TILE - 1) / TILE * TILE;
    const bool valid = (i < N_ARGS);
    const int v = valid ? is_in[i] : 0;
    const unsigned full = 0xffffffffu;
    const unsigned m_in  = __ballot_sync(full, valid && (v != 0));
    const unsigned m_out = __ballot_sync(full, valid && (v == 0));
    const int lane = threadIdx.x & 31;
    int b_in = 0, b_out = 0;
    if (lane == 0 && m_in)  b_in  = atomicAdd(&g_meta[1], __popc(m_in));
    if (lane == 0 && m_out) b_out = atomicAdd(&g_meta[2], __popc(m_out));
    b_in  = __shfl_sync(full, b_in, 0);
    b_out = __shfl_sync(full, b_out, 0);
    const unsigned lt = (1u << lane) - 1u;
    if (valid) {
        if (v) g_perm[b_in + __popc(m_in & lt)] = i;
        else   g_perm[pad + b_out + __popc(m_out & lt)] = i;
    }
}

// ---------- kernel 4: output init (trigger ent copy + zero args region) ----------
__global__ void k_outinit(const float* __restrict__ ent,
                          const int* __restrict__ trig_ent,
                          float* __restrict__ out) {
    const int total = N_TRIG * (OUTW / 4);
    for (int idx = blockIdx.x * blockDim.x + threadIdx.x; idx < total;
         idx += gridDim.x * blockDim.x) {
        const int t  = idx / (OUTW / 4);
        const int c4 = (idx % (OUTW / 4)) * 4;
        float4 v = make_float4(0.f, 0.f, 0.f, 0.f);
        if (c4 < ENT_DIM)
            v = *(const float4*)(ent + (size_t)trig_ent[t] * ENT_DIM + c4);
        *(float4*)(out + (size_t)t * OUTW + c4) = v;
    }
}

// ---------- kernel 5: gather + GEMM (packed f32x2) + atomic scatter ----------
__global__ void __launch_bounds__(256, 1)
k_gemm(const float* __restrict__ ent, const float* __restrict__ rel,
       const float* __restrict__ rtab, const float* __restrict__ Win,
       const float* __restrict__ Wout, const int* __restrict__ rtype_ids,
       const int* __restrict__ arg_trig, const int* __restrict__ arg_rel,
       const int* __restrict__ arg_ent, float* __restrict__ out) {
    extern __shared__ float xs[];                 // [TILE][KDIM]
    __shared__ int s_rel[TILE], s_ent[TILE], s_rt[TILE], s_trig[TILE], s_valid[TILE];

    const int tid  = threadIdx.x;
    const int base = blockIdx.x * TILE;

    if (tid < TILE) {
        const int pa = g_perm[base + tid];
        s_valid[tid] = pa;
        if (pa >= 0) {
            const int r = arg_rel[pa];
            s_rel[tid]  = r;
            s_rt[tid]   = rtype_ids[r];
            s_ent[tid]  = arg_ent[pa];
            s_trig[tid] = arg_trig[pa];
        }
    }
    __syncthreads();

    // Gather x rows: [rel(256) | rtype(32) | ent(288)] as float4 chunks.
    for (int idx = tid; idx < TILE * (KDIM / 4); idx += 256) {
        const int a  = idx / (KDIM / 4);
        const int c4 = (idx % (KDIM / 4)) * 4;
        float4 v = make_float4(0.f, 0.f, 0.f, 0.f);
        if (s_valid[a] >= 0) {
            if (c4 < REL_R)
                v = *(const float4*)(rel + (size_t)s_rel[a] * REL_R + c4);
            else if (c4 < REL_R + RTYPE_D)
                v = *(const float4*)(rtab + (size_t)s_rt[a] * RTYPE_D + (c4 - REL_R));
            else
                v = *(const float4*)(ent + (size_t)s_ent[a] * ENT_DIM + (c4 - REL_R - RTYPE_D));
        }
        *(float4*)(xs + a * KDIM + c4) = v;
    }
    __syncthreads();

    // Tiles are mask-homogeneous thanks to the compaction; pick W per tile.
    const int pad = (g_meta[0] + TILE - 1) / TILE * TILE;
    const float* __restrict__ W = (base < pad) ? Win : Wout;

    const int jt = tid & 31;       // column group: owns cols [8*jt, 8*jt+8)
    const int at = tid >> 5;       // arg group:    owns args [8*at, 8*at+8)
    const float* wp = W + jt * 8;
    const float* xp = xs + at * 8 * KDIM;

    ull acc[8][4];
    #pragma unroll
    for (int a = 0; a < 8; a++)
        #pragma unroll
        for (int c = 0; c < 4; c++) acc[a][c] = 0ull;

    #pragma unroll 2
    for (int k = 0; k < KDIM; k++) {
        const float4 wA = *(const float4*)(wp + (size_t)k * ROLE);
        const float4 wB = *(const float4*)(wp + (size_t)k * ROLE + 4);
        const ull w0 = pk2(wA.x, wA.y), w1 = pk2(wA.z, wA.w);
        const ull w2 = pk2(wB.x, wB.y), w3 = pk2(wB.z, wB.w);
        #pragma unroll
        for (int a = 0; a < 8; a++) {
            const float xv = xp[a * KDIM + k];   // LDS broadcast across warp
            const ull x2 = pk2(xv, xv);
            ffma2(acc[a][0], x2, w0);
            ffma2(acc[a][1], x2, w1);
            ffma2(acc[a][2], x2, w2);
            ffma2(acc[a][3], x2, w3);
        }
    }

    // Scatter: segment-sum into out[trig][288 + col]
    #pragma unroll
    for (int a = 0; a < 8; a++) {
        const int ai = at * 8 + a;
        if (s_valid[ai] < 0) continue;
        float* p = out + (size_t)s_trig[ai] * OUTW + ENT_DIM + jt * 8;
        #pragma unroll
        for (int c = 0; c < 4; c++) {
            float lo, hi;
            upk2(acc[a][c], lo, hi);
            atomicAdd(p + c * 2,     lo);
            atomicAdd(p + c * 2 + 1, hi);
        }
    }
}

extern "C" void kernel_launch(void* const* d_in, const int* in_sizes, int n_in,
                              void* d_out, int out_size) {
    const float* ent       = (const float*)d_in[0];
    const float* rel       = (const float*)d_in[1];
    const float* rtab      = (const float*)d_in[2];
    const float* Win       = (const float*)d_in[3];
    const float* Wout      = (const float*)d_in[4];
    const int*   rtype_ids = (const int*)d_in[5];
    const int*   trig_ent  = (const int*)d_in[6];
    const int*   arg_trig  = (const int*)d_in[7];
    const int*   arg_rel   = (const int*)d_in[8];
    const int*   arg_ent   = (const int*)d_in[9];
    const int*   arg_is_in = (const int*)d_in[10];
    float* out = (float*)d_out;

    const int smem = TILE * KDIM * (int)sizeof(float);   // 147456 B
    cudaFuncSetAttribute(k_gemm, cudaFuncAttributeMaxDynamicSharedMemorySize, smem);

    k_init<<<256, 256>>>();
    k_count<<<128, 256>>>(arg_is_in);
    k_place<<<(N_ARGS + 255) / 256, 256>>>(arg_is_in);
    k_outinit<<<1024, 256>>>(ent, trig_ent, out);
    k_gemm<<<NTILES, 256, smem>>>(ent, rel, rtab, Win, Wout, rtype_ids,
                                  arg_trig, arg_rel, arg_ent, out);
}

// round 11
// speedup vs baseline: 3.0518x; 3.0518x over previous
#include <cuda_runtime.h>
#include <cuda_bf16.h>
#include <cstdint>

// Problem constants
#define N_ENT   100000
#define N_REL   250000
#define N_TRIG  50000
#define N_ARGS  250000
#define ENT_DIM 288
#define REL_R   256
#define RTYPE_D 32
#define ROLE    256
#define KDIM    576
#define OUTW    544

#define TILE_M  128
#define NT      1955
#define PERM_SZ (NT * TILE_M)

#define KC      64                 // k per chunk
#define NCHUNK  (KDIM / KC)        // 9
#define WSTRIDE 72                 // bf16 elems per smem row (144 B = 36 banks, conflict-free)
#define ROWB    144                // bytes per row

#define A_BYTES   (TILE_M * ROWB)  // 18432
#define B_BYTES   (ROLE * ROWB)    // 36864
#define OFF_AH    0
#define OFF_AL    A_BYTES
#define OFF_W     (2 * A_BYTES)    // then 2 buffers of (Bh | Bl)
#define WBUF_B    (2 * B_BYTES)    // 73728 per buffer
#define SMEM_DYN  (2 * A_BYTES + 2 * WBUF_B)   // 184320

#define THREADS 512

typedef unsigned long long ull;

// ---------------- scratch globals ----------------
__device__ int g_perm[PERM_SZ];
__device__ int g_meta[4];
// Pre-split W, padded chunked B layout: [chunk][n][WSTRIDE] bf16 (k-contiguous rows)
#define WCH (ROLE * WSTRIDE)       // 18432 elems per chunk
__device__ unsigned short g_WhIn [NCHUNK * WCH];
__device__ unsigned short g_WlIn [NCHUNK * WCH];
__device__ unsigned short g_WhOut[NCHUNK * WCH];
__device__ unsigned short g_WlOut[NCHUNK * WCH];

// ---------------- helpers ----------------
__device__ __forceinline__ unsigned sptr(const void* p) {
    return (unsigned)__cvta_generic_to_shared(p);
}
__device__ __forceinline__ void mma_bf16(float& d0, float& d1, float& d2, float& d3,
                                         unsigned a0, unsigned a1, unsigned a2, unsigned a3,
                                         unsigned b0, unsigned b1) {
    asm volatile(
        "mma.sync.aligned.m16n8k16.row.col.f32.bf16.bf16.f32 "
        "{%0,%1,%2,%3}, {%4,%5,%6,%7}, {%8,%9}, {%0,%1,%2,%3};"
        : "+f"(d0), "+f"(d1), "+f"(d2), "+f"(d3)
        : "r"(a0), "r"(a1), "r"(a2), "r"(a3), "r"(b0), "r"(b1));
}
__device__ __forceinline__ void cp16(unsigned s, const void* g) {
    asm volatile("cp.async.ca.shared.global [%0], [%1], 16;" :: "r"(s), "l"(g));
}
__device__ __forceinline__ void red_v2(float* p, float a, float b) {
    asm volatile("red.global.add.v2.f32 [%0], {%1, %2};" :: "l"(p), "f"(a), "f"(b) : "memory");
}

// ---------------- kernel 1: reset scratch ----------------
__global__ void k_init() {
    int i = blockIdx.x * blockDim.x + threadIdx.x;
    for (; i < PERM_SZ; i += gridDim.x * blockDim.x) g_perm[i] = -1;
    if (blockIdx.x == 0 && threadIdx.x == 0) {
        g_meta[0] = 0; g_meta[1] = 0; g_meta[2] = 0; g_meta[3] = 0;
    }
}

// ---------------- kernel 2: count in-args ----------------
__global__ void k_count(const int* __restrict__ is_in) {
    int s = 0;
    for (int i = blockIdx.x * blockDim.x + threadIdx.x; i < N_ARGS;
         i += gridDim.x * blockDim.x)
        s += is_in[i];
    #pragma unroll
    for (int o = 16; o; o >>= 1) s += __shfl_down_sync(0xffffffffu, s, o);
    __shared__ int sh[8];
    if ((threadIdx.x & 31) == 0) sh[threadIdx.x >> 5] = s;
    __syncthreads();
    if (threadIdx.x < 8) {
        s = sh[threadIdx.x];
        #pragma unroll
        for (int o = 4; o; o >>= 1) s += __shfl_down_sync(0xffu, s, o);
        if (threadIdx.x == 0) atomicAdd(&g_meta[0], s);
    }
}

// ---------------- kernel 3: place args ----------------
__global__ void k_place(const int* __restrict__ is_in) {
    const int i = blockIdx.x * blockDim.x + threadIdx.x;
    const int pad = (g_meta[0] + TILE_M - 1) / TILE_M * TILE_M;
    const bool valid = (i < N_ARGS);
    const int v = valid ? is_in[i] : 0;
    const unsigned full = 0xffffffffu;
    const unsigned m_in  = __ballot_sync(full, valid && (v != 0));
    const unsigned m_out = __ballot_sync(full, valid && (v == 0));
    const int lane = threadIdx.x & 31;
    int b_in = 0, b_out = 0;
    if (lane == 0 && m_in)  b_in  = atomicAdd(&g_meta[1], __popc(m_in));
    if (lane == 0 && m_out) b_out = atomicAdd(&g_meta[2], __popc(m_out));
    b_in  = __shfl_sync(full, b_in, 0);
    b_out = __shfl_sync(full, b_out, 0);
    const unsigned lt = (1u << lane) - 1u;
    if (valid) {
        if (v) g_perm[b_in + __popc(m_in & lt)] = i;
        else   g_perm[pad + b_out + __popc(m_out & lt)] = i;
    }
}

// ---------------- kernel 4: pre-split W (bf16 hi/lo, padded chunked B layout) ----------------
__global__ void k_prepW(const float* __restrict__ Win, const float* __restrict__ Wout) {
    const int i = blockIdx.x * blockDim.x + threadIdx.x;
    if (i >= KDIM * ROLE) return;
    const int k = i / ROLE, n = i % ROLE;
    const int chunk = k >> 6, kk = k & 63;
    const int pos = chunk * WCH + n * WSTRIDE + kk;

    float a = Win[i];
    __nv_bfloat16 h = __float2bfloat16(a);
    __nv_bfloat16 l = __float2bfloat16(a - __bfloat162float(h));
    g_WhIn[pos] = __bfloat16_as_ushort(h);
    g_WlIn[pos] = __bfloat16_as_ushort(l);

    a = Wout[i];
    h = __float2bfloat16(a);
    l = __float2bfloat16(a - __bfloat162float(h));
    g_WhOut[pos] = __bfloat16_as_ushort(h);
    g_WlOut[pos] = __bfloat16_as_ushort(l);
}

// ---------------- kernel 5: output init ----------------
__global__ void k_outinit(const float* __restrict__ ent,
                          const int* __restrict__ trig_ent,
                          float* __restrict__ out) {
    const int total = N_TRIG * (OUTW / 4);
    for (int idx = blockIdx.x * blockDim.x + threadIdx.x; idx < total;
         idx += gridDim.x * blockDim.x) {
        const int t  = idx / (OUTW / 4);
        const int c4 = (idx % (OUTW / 4)) * 4;
        float4 v = make_float4(0.f, 0.f, 0.f, 0.f);
        if (c4 < ENT_DIM)
            v = *(const float4*)(ent + (size_t)trig_ent[t] * ENT_DIM + c4);
        *(float4*)(out + (size_t)t * OUTW + c4) = v;
    }
}

// ---------------- kernel 6: HMMA bf16x3 GEMM + v2-atomic scatter ----------------
__global__ void __launch_bounds__(THREADS, 1)
k_gemm_mma(const float* __restrict__ ent, const float* __restrict__ rel,
           const float* __restrict__ rtab, const int* __restrict__ rtype_ids,
           const int* __restrict__ arg_trig, const int* __restrict__ arg_rel,
           const int* __restrict__ arg_ent, float* __restrict__ out) {
    extern __shared__ char sm[];
    __shared__ int s_rel[TILE_M], s_rt[TILE_M], s_ent[TILE_M], s_trig[TILE_M], s_valid[TILE_M];

    const int tid  = threadIdx.x;
    const int wid  = tid >> 5;
    const int lane = tid & 31;
    const int g    = lane >> 2;      // fragment group row
    const int tig  = lane & 3;       // thread-in-group
    const int mrow0 = (wid & 7) * 16;
    const int nhalf = (wid >> 3) * 128;

    const int base = blockIdx.x * TILE_M;
    if (tid < TILE_M) {
        const int pa = g_perm[base + tid];
        s_valid[tid] = pa;
        if (pa >= 0) {
            const int r = arg_rel[pa];
            s_rel[tid]  = r;
            s_rt[tid]   = rtype_ids[r];
            s_ent[tid]  = arg_ent[pa];
            s_trig[tid] = arg_trig[pa];
        }
    }
    __syncthreads();

    const int pad = (g_meta[0] + TILE_M - 1) / TILE_M * TILE_M;
    const unsigned short* __restrict__ wh = (base < pad) ? g_WhIn : g_WhOut;
    const unsigned short* __restrict__ wl = (base < pad) ? g_WlIn : g_WlOut;

    char* A_h = sm + OFF_AH;
    char* A_l = sm + OFF_AL;

    // W prefetch helper: one chunk's Bh+Bl into buffer b
    auto prefetchW = [&](int c, int b) {
        char* dh = sm + OFF_W + b * WBUF_B;
        char* dl = dh + B_BYTES;
        const char* gh = (const char*)(wh + c * WCH);
        const char* gl = (const char*)(wl + c * WCH);
        #pragma unroll
        for (int j = 0; j < 5; j++) {
            const int idx = tid + j * THREADS;
            if (idx < B_BYTES / 16) {
                cp16(sptr(dh + idx * 16), gh + idx * 16);
                cp16(sptr(dl + idx * 16), gl + idx * 16);
            }
        }
        asm volatile("cp.async.commit_group;" ::: "memory");
    };

    // accumulators: 16 n-tiles x 4
    float D[16][4];
    #pragma unroll
    for (int t = 0; t < 16; t++) {
        D[t][0] = 0.f; D[t][1] = 0.f; D[t][2] = 0.f; D[t][3] = 0.f;
    }

    // per-thread fragment base offsets (bytes)
    const int aoff = (mrow0 + g) * ROWB + tig * 4;
    const int boff = (nhalf + g) * ROWB + tig * 4;

    prefetchW(0, 0);

    for (int c = 0; c < NCHUNK; c++) {
        const int b = c & 1;
        if (c + 1 < NCHUNK) prefetchW(c + 1, (c + 1) & 1);

        // ---- gather X chunk, split to bf16 hi/lo, store to A smem ----
        {
            const int ck = c * KC;
            #pragma unroll
            for (int j = 0; j < 4; j++) {
                const int idx = tid + j * THREADS;       // 2048 float4 tasks
                const int row = idx >> 4;
                const int gq  = idx & 15;
                const int k0  = ck + gq * 4;
                float4 v = make_float4(0.f, 0.f, 0.f, 0.f);
                if (s_valid[row] >= 0) {
                    if (k0 < REL_R)
                        v = *(const float4*)(rel + (size_t)s_rel[row] * REL_R + k0);
                    else if (k0 < REL_R + RTYPE_D)
                        v = *(const float4*)(rtab + (size_t)s_rt[row] * RTYPE_D + (k0 - REL_R));
                    else
                        v = *(const float4*)(ent + (size_t)s_ent[row] * ENT_DIM + (k0 - REL_R - RTYPE_D));
                }
                __nv_bfloat16 h0 = __float2bfloat16(v.x);
                __nv_bfloat16 h1 = __float2bfloat16(v.y);
                __nv_bfloat16 h2 = __float2bfloat16(v.z);
                __nv_bfloat16 h3 = __float2bfloat16(v.w);
                __nv_bfloat16 l0 = __float2bfloat16(v.x - __bfloat162float(h0));
                __nv_bfloat16 l1 = __float2bfloat16(v.y - __bfloat162float(h1));
                __nv_bfloat16 l2 = __float2bfloat16(v.z - __bfloat162float(h2));
                __nv_bfloat16 l3 = __float2bfloat16(v.w - __bfloat162float(h3));
                uint2 uh, ul;
                uh.x = (unsigned)__bfloat16_as_ushort(h0) | ((unsigned)__bfloat16_as_ushort(h1) << 16);
                uh.y = (unsigned)__bfloat16_as_ushort(h2) | ((unsigned)__bfloat16_as_ushort(h3) << 16);
                ul.x = (unsigned)__bfloat16_as_ushort(l0) | ((unsigned)__bfloat16_as_ushort(l1) << 16);
                ul.y = (unsigned)__bfloat16_as_ushort(l2) | ((unsigned)__bfloat16_as_ushort(l3) << 16);
                const int so = row * ROWB + gq * 8;
                *(uint2*)(A_h + so) = uh;
                *(uint2*)(A_l + so) = ul;
            }
        }

        if (c + 1 < NCHUNK)
            asm volatile("cp.async.wait_group 1;" ::: "memory");
        else
            asm volatile("cp.async.wait_group 0;" ::: "memory");
        __syncthreads();

        // ---- compute: 3 passes (HH, HL, LH) x 4 k16-steps x 16 n-tiles ----
        const char* Bh = sm + OFF_W + b * WBUF_B;
        const char* Bl = Bh + B_BYTES;
        #pragma unroll
        for (int pass = 0; pass < 3; pass++) {
            const char* Ab = (pass == 2) ? A_l : A_h;
            const char* Bb = (pass == 1) ? Bl : Bh;
            #pragma unroll
            for (int ks = 0; ks < 4; ks++) {
                const char* ap = Ab + aoff + ks * 32;
                const unsigned a0 = *(const unsigned*)(ap);
                const unsigned a1 = *(const unsigned*)(ap + 8 * ROWB);
                const unsigned a2 = *(const unsigned*)(ap + 16);
                const unsigned a3 = *(const unsigned*)(ap + 8 * ROWB + 16);
                const char* bp = Bb + boff + ks * 32;
                #pragma unroll
                for (int nt = 0; nt < 16; nt++) {
                    const unsigned b0 = *(const unsigned*)(bp + nt * 8 * ROWB);
                    const unsigned b1 = *(const unsigned*)(bp + nt * 8 * ROWB + 16);
                    mma_bf16(D[nt][0], D[nt][1], D[nt][2], D[nt][3],
                             a0, a1, a2, a3, b0, b1);
                }
            }
        }
        __syncthreads();
    }

    // ---- epilogue: scatter into out[trig][288+col] via v2 atomics ----
    const int r0 = mrow0 + g;
    const int r1 = r0 + 8;
    const int ok0 = (s_valid[r0] >= 0);
    const int ok1 = (s_valid[r1] >= 0);
    float* p0 = ok0 ? (out + (size_t)s_trig[r0] * OUTW + ENT_DIM + nhalf + tig * 2) : out;
    float* p1 = ok1 ? (out + (size_t)s_trig[r1] * OUTW + ENT_DIM + nhalf + tig * 2) : out;
    #pragma unroll
    for (int nt = 0; nt < 16; nt++) {
        if (ok0) red_v2(p0 + nt * 8, D[nt][0], D[nt][1]);
        if (ok1) red_v2(p1 + nt * 8, D[nt][2], D[nt][3]);
    }
}

extern "C" void kernel_launch(void* const* d_in, const int* in_sizes, int n_in,
                              void* d_out, int out_size) {
    const float* ent       = (const float*)d_in[0];
    const float* rel       = (const float*)d_in[1];
    const float* rtab      = (const float*)d_in[2];
    const float* Win       = (const float*)d_in[3];
    const float* Wout      = (const float*)d_in[4];
    const int*   rtype_ids = (const int*)d_in[5];
    const int*   trig_ent  = (const int*)d_in[6];
    const int*   arg_trig  = (const int*)d_in[7];
    const int*   arg_rel   = (const int*)d_in[8];
    const int*   arg_ent   = (const int*)d_in[9];
    const int*   arg_is_in = (const int*)d_in[10];
    float* out = (float*)d_out;

    cudaFuncSetAttribute(k_gemm_mma, cudaFuncAttributeMaxDynamicSharedMemorySize, SMEM_DYN);

    k_init<<<256, 256>>>();
    k_count<<<128, 256>>>(arg_is_in);
    k_place<<<(N_ARGS + 255) / 256, 256>>>(arg_is_in);
    k_prepW<<<(KDIM * ROLE + 255) / 256, 256>>>(Win, Wout);
    k_outinit<<<1024, 256>>>(ent, trig_ent, out);
    k_gemm_mma<<<NT, THREADS, SMEM_DYN>>>(ent, rel, rtab, rtype_ids,
                                          arg_trig, arg_rel, arg_ent, out);
}

// round 12
// speedup vs baseline: 3.2720x; 1.0721x over previous
#include <cuda_runtime.h>
#include <cuda_bf16.h>
#include <cstdint>

// Problem constants
#define N_ENT   100000
#define N_REL   250000
#define N_TRIG  50000
#define N_ARGS  250000
#define ENT_DIM 288
#define REL_R   256
#define RTYPE_D 32
#define ROLE    256
#define KDIM    576
#define OUTW    544

#define TILE_M  128
#define NT      1955
#define PERM_SZ (NT * TILE_M)

#define KC      64                 // k per chunk
#define NCHUNK  (KDIM / KC)        // 9
#define WSTRIDE 72                 // bf16 elems per smem row (144 B, conflict-free)
#define ROWB    144                // bytes per row

#define A_BYTES   (TILE_M * ROWB)  // 18432
#define B_BYTES   (ROLE * ROWB)    // 36864
#define OFF_AH    0
#define OFF_AL    A_BYTES
#define OFF_W     (2 * A_BYTES)
#define WBUF_B    (2 * B_BYTES)    // 73728 per buffer (Bh | Bl)
#define SMEM_DYN  (2 * A_BYTES + 2 * WBUF_B)   // 184320

#define THREADS 512

typedef unsigned long long ull;

// ---------------- scratch globals ----------------
__device__ int g_perm[PERM_SZ];
__device__ int g_meta[4];
#define WCH (ROLE * WSTRIDE)       // 18432 bf16 per chunk
__device__ unsigned short g_WhIn [NCHUNK * WCH];
__device__ unsigned short g_WlIn [NCHUNK * WCH];
__device__ unsigned short g_WhOut[NCHUNK * WCH];
__device__ unsigned short g_WlOut[NCHUNK * WCH];

// ---------------- helpers ----------------
__device__ __forceinline__ unsigned sptr(const void* p) {
    return (unsigned)__cvta_generic_to_shared(p);
}
__device__ __forceinline__ void mma_bf16(float* d, const unsigned* a, unsigned b0, unsigned b1) {
    asm volatile(
        "mma.sync.aligned.m16n8k16.row.col.f32.bf16.bf16.f32 "
        "{%0,%1,%2,%3}, {%4,%5,%6,%7}, {%8,%9}, {%0,%1,%2,%3};"
        : "+f"(d[0]), "+f"(d[1]), "+f"(d[2]), "+f"(d[3])
        : "r"(a[0]), "r"(a[1]), "r"(a[2]), "r"(a[3]), "r"(b0), "r"(b1));
}
__device__ __forceinline__ void ldsm4(unsigned* r, unsigned addr) {
    asm volatile("ldmatrix.sync.aligned.m8n8.x4.shared.b16 {%0,%1,%2,%3}, [%4];"
                 : "=r"(r[0]), "=r"(r[1]), "=r"(r[2]), "=r"(r[3]) : "r"(addr));
}
__device__ __forceinline__ void cp16(unsigned s, const void* g) {
    asm volatile("cp.async.ca.shared.global [%0], [%1], 16;" :: "r"(s), "l"(g));
}
__device__ __forceinline__ void red_v2(float* p, float a, float b) {
    asm volatile("red.global.add.v2.f32 [%0], {%1, %2};" :: "l"(p), "f"(a), "f"(b) : "memory");
}

// ---------------- kernel 1: reset scratch ----------------
__global__ void k_init() {
    int i = blockIdx.x * blockDim.x + threadIdx.x;
    for (; i < PERM_SZ; i += gridDim.x * blockDim.x) g_perm[i] = -1;
    if (blockIdx.x == 0 && threadIdx.x == 0) {
        g_meta[0] = 0; g_meta[1] = 0; g_meta[2] = 0; g_meta[3] = 0;
    }
}

// ---------------- kernel 2: count in-args ----------------
__global__ void k_count(const int* __restrict__ is_in) {
    int s = 0;
    for (int i = blockIdx.x * blockDim.x + threadIdx.x; i < N_ARGS;
         i += gridDim.x * blockDim.x)
        s += is_in[i];
    #pragma unroll
    for (int o = 16; o; o >>= 1) s += __shfl_down_sync(0xffffffffu, s, o);
    __shared__ int sh[8];
    if ((threadIdx.x & 31) == 0) sh[threadIdx.x >> 5] = s;
    __syncthreads();
    if (threadIdx.x < 8) {
        s = sh[threadIdx.x];
        #pragma unroll
        for (int o = 4; o; o >>= 1) s += __shfl_down_sync(0xffu, s, o);
        if (threadIdx.x == 0) atomicAdd(&g_meta[0], s);
    }
}

// ---------------- kernel 3: place args ----------------
__global__ void k_place(const int* __restrict__ is_in) {
    const int i = blockIdx.x * blockDim.x + threadIdx.x;
    const int pad = (g_meta[0] + TILE_M - 1) / TILE_M * TILE_M;
    const bool valid = (i < N_ARGS);
    const int v = valid ? is_in[i] : 0;
    const unsigned full = 0xffffffffu;
    const unsigned m_in  = __ballot_sync(full, valid && (v != 0));
    const unsigned m_out = __ballot_sync(full, valid && (v == 0));
    const int lane = threadIdx.x & 31;
    int b_in = 0, b_out = 0;
    if (lane == 0 && m_in)  b_in  = atomicAdd(&g_meta[1], __popc(m_in));
    if (lane == 0 && m_out) b_out = atomicAdd(&g_meta[2], __popc(m_out));
    b_in  = __shfl_sync(full, b_in, 0);
    b_out = __shfl_sync(full, b_out, 0);
    const unsigned lt = (1u << lane) - 1u;
    if (valid) {
        if (v) g_perm[b_in + __popc(m_in & lt)] = i;
        else   g_perm[pad + b_out + __popc(m_out & lt)] = i;
    }
}

// ---------------- kernel 4: pre-split W ----------------
__global__ void k_prepW(const float* __restrict__ Win, const float* __restrict__ Wout) {
    const int i = blockIdx.x * blockDim.x + threadIdx.x;
    if (i >= KDIM * ROLE) return;
    const int k = i / ROLE, n = i % ROLE;
    const int chunk = k >> 6, kk = k & 63;
    const int pos = chunk * WCH + n * WSTRIDE + kk;

    float a = Win[i];
    __nv_bfloat16 h = __float2bfloat16(a);
    __nv_bfloat16 l = __float2bfloat16(a - __bfloat162float(h));
    g_WhIn[pos] = __bfloat16_as_ushort(h);
    g_WlIn[pos] = __bfloat16_as_ushort(l);

    a = Wout[i];
    h = __float2bfloat16(a);
    l = __float2bfloat16(a - __bfloat162float(h));
    g_WhOut[pos] = __bfloat16_as_ushort(h);
    g_WlOut[pos] = __bfloat16_as_ushort(l);
}

// ---------------- kernel 5: output init ----------------
__global__ void k_outinit(const float* __restrict__ ent,
                          const int* __restrict__ trig_ent,
                          float* __restrict__ out) {
    const int total = N_TRIG * (OUTW / 4);
    for (int idx = blockIdx.x * blockDim.x + threadIdx.x; idx < total;
         idx += gridDim.x * blockDim.x) {
        const int t  = idx / (OUTW / 4);
        const int c4 = (idx % (OUTW / 4)) * 4;
        float4 v = make_float4(0.f, 0.f, 0.f, 0.f);
        if (c4 < ENT_DIM)
            v = *(const float4*)(ent + (size_t)trig_ent[t] * ENT_DIM + c4);
        *(float4*)(out + (size_t)t * OUTW + c4) = v;
    }
}

// ---------------- kernel 6: HMMA bf16x3, LDSM fragments, m32n64 warp tiles ----------------
__global__ void __launch_bounds__(THREADS, 1)
k_gemm_mma(const float* __restrict__ ent, const float* __restrict__ rel,
           const float* __restrict__ rtab, const int* __restrict__ rtype_ids,
           const int* __restrict__ arg_trig, const int* __restrict__ arg_rel,
           const int* __restrict__ arg_ent, float* __restrict__ out) {
    extern __shared__ char sm[];
    __shared__ int s_rel[TILE_M], s_rt[TILE_M], s_ent[TILE_M], s_trig[TILE_M], s_valid[TILE_M];

    const int tid  = threadIdx.x;
    const int wid  = tid >> 5;
    const int lane = tid & 31;
    const int g    = lane >> 2;
    const int tig  = lane & 3;
    const int wm   = wid & 3;        // m tile: rows [wm*32, wm*32+32)
    const int wn   = wid >> 2;       // n tile: cols [wn*64, wn*64+64)

    const unsigned sbase = sptr(sm);

    const int base = blockIdx.x * TILE_M;
    if (tid < TILE_M) {
        const int pa = g_perm[base + tid];
        s_valid[tid] = pa;
        if (pa >= 0) {
            const int r = arg_rel[pa];
            s_rel[tid]  = r;
            s_rt[tid]   = rtype_ids[r];
            s_ent[tid]  = arg_ent[pa];
            s_trig[tid] = arg_trig[pa];
        }
    }
    __syncthreads();

    const int pad = (g_meta[0] + TILE_M - 1) / TILE_M * TILE_M;
    const unsigned short* __restrict__ wh = (base < pad) ? g_WhIn : g_WhOut;
    const unsigned short* __restrict__ wl = (base < pad) ? g_WlIn : g_WlOut;

    char* A_h = sm + OFF_AH;
    char* A_l = sm + OFF_AL;

    auto prefetchW = [&](int c, int b) {
        char* dh = sm + OFF_W + b * WBUF_B;
        char* dl = dh + B_BYTES;
        const char* gh = (const char*)(wh + c * WCH);
        const char* gl = (const char*)(wl + c * WCH);
        #pragma unroll
        for (int j = 0; j < 5; j++) {
            const int idx = tid + j * THREADS;
            if (idx < B_BYTES / 16) {
                cp16(sptr(dh + idx * 16), gh + idx * 16);
                cp16(sptr(dl + idx * 16), gl + idx * 16);
            }
        }
        asm volatile("cp.async.commit_group;" ::: "memory");
    };

    // accumulators: [msub][nt][4]
    float D[2][8][4];
    #pragma unroll
    for (int ms = 0; ms < 2; ms++)
        #pragma unroll
        for (int t = 0; t < 8; t++) {
            D[ms][t][0] = 0.f; D[ms][t][1] = 0.f; D[ms][t][2] = 0.f; D[ms][t][3] = 0.f;
        }

    // ldmatrix per-lane offsets (bytes, within A / B tiles)
    // A x4: mat0=m[0:8)k[0:8), mat1=m[8:16)k[0:8), mat2=m[0:8)k[8:16), mat3=m[8:16)k[8:16)
    const unsigned a_lane = (unsigned)(((lane & 7) + ((lane >> 3) & 1) * 8) * ROWB
                                       + ((lane >> 4) & 1) * 16);
    const unsigned a_off0 = (unsigned)(wm * 32 * ROWB) + a_lane;
    const unsigned a_off1 = a_off0 + 16 * ROWB;
    // B x4: mat0=(nt,b0), mat1=(nt,b1), mat2=(nt+1,b0), mat3=(nt+1,b1)
    const unsigned b_lane = (unsigned)((lane & 7) * ROWB + ((lane >> 3) & 1) * 16
                                       + ((lane >> 4) & 1) * 8 * ROWB);
    const unsigned b_off  = (unsigned)(wn * 64 * ROWB) + b_lane;

    prefetchW(0, 0);

    for (int c = 0; c < NCHUNK; c++) {
        const int b = c & 1;
        if (c + 1 < NCHUNK) prefetchW(c + 1, (c + 1) & 1);

        // ---- gather X chunk, split bf16 hi/lo into A smem ----
        {
            const int ck = c * KC;
            #pragma unroll
            for (int j = 0; j < 4; j++) {
                const int idx = tid + j * THREADS;
                const int row = idx >> 4;
                const int gq  = idx & 15;
                const int k0  = ck + gq * 4;
                float4 v = make_float4(0.f, 0.f, 0.f, 0.f);
                if (s_valid[row] >= 0) {
                    if (k0 < REL_R)
                        v = *(const float4*)(rel + (size_t)s_rel[row] * REL_R + k0);
                    else if (k0 < REL_R + RTYPE_D)
                        v = *(const float4*)(rtab + (size_t)s_rt[row] * RTYPE_D + (k0 - REL_R));
                    else
                        v = *(const float4*)(ent + (size_t)s_ent[row] * ENT_DIM + (k0 - REL_R - RTYPE_D));
                }
                __nv_bfloat16 h0 = __float2bfloat16(v.x);
                __nv_bfloat16 h1 = __float2bfloat16(v.y);
                __nv_bfloat16 h2 = __float2bfloat16(v.z);
                __nv_bfloat16 h3 = __float2bfloat16(v.w);
                __nv_bfloat16 l0 = __float2bfloat16(v.x - __bfloat162float(h0));
                __nv_bfloat16 l1 = __float2bfloat16(v.y - __bfloat162float(h1));
                __nv_bfloat16 l2 = __float2bfloat16(v.z - __bfloat162float(h2));
                __nv_bfloat16 l3 = __float2bfloat16(v.w - __bfloat162float(h3));
                uint2 uh, ul;
                uh.x = (unsigned)__bfloat16_as_ushort(h0) | ((unsigned)__bfloat16_as_ushort(h1) << 16);
                uh.y = (unsigned)__bfloat16_as_ushort(h2) | ((unsigned)__bfloat16_as_ushort(h3) << 16);
                ul.x = (unsigned)__bfloat16_as_ushort(l0) | ((unsigned)__bfloat16_as_ushort(l1) << 16);
                ul.y = (unsigned)__bfloat16_as_ushort(l2) | ((unsigned)__bfloat16_as_ushort(l3) << 16);
                const int so = row * ROWB + gq * 8;
                *(uint2*)(A_h + so) = uh;
                *(uint2*)(A_l + so) = ul;
            }
        }

        if (c + 1 < NCHUNK)
            asm volatile("cp.async.wait_group 1;" ::: "memory");
        else
            asm volatile("cp.async.wait_group 0;" ::: "memory");
        __syncthreads();

        const unsigned sAh = sbase + OFF_AH;
        const unsigned sAl = sbase + OFF_AL;
        const unsigned sBh = sbase + OFF_W + b * WBUF_B;
        const unsigned sBl = sBh + B_BYTES;

        #pragma unroll
        for (int ks = 0; ks < 4; ks++) {
            const unsigned ko = (unsigned)(ks * 32);
            unsigned ah[8], al[8], bh[16], bl[16];
            ldsm4(ah,     sAh + a_off0 + ko);
            ldsm4(ah + 4, sAh + a_off1 + ko);
            ldsm4(al,     sAl + a_off0 + ko);
            ldsm4(al + 4, sAl + a_off1 + ko);
            #pragma unroll
            for (int p = 0; p < 4; p++) {
                ldsm4(bh + p * 4, sBh + b_off + (unsigned)(p * 16 * ROWB) + ko);
                ldsm4(bl + p * 4, sBl + b_off + (unsigned)(p * 16 * ROWB) + ko);
            }
            #pragma unroll
            for (int ms = 0; ms < 2; ms++) {
                const unsigned* aH = ah + ms * 4;
                const unsigned* aL = al + ms * 4;
                #pragma unroll
                for (int nt = 0; nt < 8; nt++) {
                    const int bi = (nt >> 1) * 4 + (nt & 1) * 2;
                    mma_bf16(D[ms][nt], aH, bh[bi], bh[bi + 1]);   // HH
                    mma_bf16(D[ms][nt], aH, bl[bi], bl[bi + 1]);   // HL
                    mma_bf16(D[ms][nt], aL, bh[bi], bh[bi + 1]);   // LH
                }
            }
        }
        __syncthreads();
    }

    // ---- epilogue: scatter via v2 atomics ----
    #pragma unroll
    for (int ms = 0; ms < 2; ms++) {
        #pragma unroll
        for (int half = 0; half < 2; half++) {
            const int row = wm * 32 + ms * 16 + g + half * 8;
            if (s_valid[row] < 0) continue;
            float* p = out + (size_t)s_trig[row] * OUTW + ENT_DIM + wn * 64 + tig * 2;
            #pragma unroll
            for (int nt = 0; nt < 8; nt++)
                red_v2(p + nt * 8, D[ms][nt][half * 2], D[ms][nt][half * 2 + 1]);
        }
    }
}

extern "C" void kernel_launch(void* const* d_in, const int* in_sizes, int n_in,
                              void* d_out, int out_size) {
    const float* ent       = (const float*)d_in[0];
    const float* rel       = (const float*)d_in[1];
    const float* rtab      = (const float*)d_in[2];
    const float* Win       = (const float*)d_in[3];
    const float* Wout      = (const float*)d_in[4];
    const int*   rtype_ids = (const int*)d_in[5];
    const int*   trig_ent  = (const int*)d_in[6];
    const int*   arg_trig  = (const int*)d_in[7];
    const int*   arg_rel   = (const int*)d_in[8];
    const int*   arg_ent   = (const int*)d_in[9];
    const int*   arg_is_in = (const int*)d_in[10];
    float* out = (float*)d_out;

    cudaFuncSetAttribute(k_gemm_mma, cudaFuncAttributeMaxDynamicSharedMemorySize, SMEM_DYN);

    k_init<<<256, 256>>>();
    k_count<<<128, 256>>>(arg_is_in);
    k_place<<<(N_ARGS + 255) / 256, 256>>>(arg_is_in);
    k_prepW<<<(KDIM * ROLE + 255) / 256, 256>>>(Win, Wout);
    k_outinit<<<1024, 256>>>(ent, trig_ent, out);
    k_gemm_mma<<<NT, THREADS, SMEM_DYN>>>(ent, rel, rtab, rtype_ids,
                                          arg_trig, arg_rel, arg_ent, out);
}

// round 16
// speedup vs baseline: 3.9374x; 1.2034x over previous
#include <cuda_runtime.h>
#include <cuda_bf16.h>
#include <cuda_fp16.h>
#include <cstdint>

// Problem constants
#define N_ENT   100000
#define N_REL   250000
#define N_TRIG  50000
#define N_ARGS  250000
#define ENT_DIM 288
#define REL_R   256
#define RTYPE_D 32
#define ROLE    256
#define KDIM    576
#define OUTW    544

#define TILE_M  128
#define NT      1955
#define PERM_SZ (NT * TILE_M)

#define KC      64                 // k per chunk
#define NCHUNK  (KDIM / KC)        // 9
#define WSTRIDE 72                 // fp16 elems per smem row (144 B, conflict-free)
#define ROWB    144                // bytes per row

#define A_BYTES   (TILE_M * ROWB)  // 18432 (single A tile, fp16)
#define B_BYTES   (ROLE * ROWB)    // 36864
#define OFF_W     A_BYTES          // W double buffer after A
#define WBUF_B    (2 * B_BYTES)    // 73728 per buffer (Wh | Wl)
#define SMEM_DYN  (A_BYTES + 2 * WBUF_B)   // 165888

#define THREADS 512
#define WSCALE    2048.0f
#define INV_SCALE 4.8828125e-4f    // 1/2048

typedef unsigned long long ull;

// ---------------- scratch globals ----------------
__device__ int g_perm[PERM_SZ];
__device__ int g_meta[4];
#define WCH (ROLE * WSTRIDE)       // 18432 fp16 per chunk
__device__ unsigned short g_WhIn [NCHUNK * WCH];
__device__ unsigned short g_WlIn [NCHUNK * WCH];
__device__ unsigned short g_WhOut[NCHUNK * WCH];
__device__ unsigned short g_WlOut[NCHUNK * WCH];

// ---------------- helpers ----------------
__device__ __forceinline__ unsigned sptr(const void* p) {
    return (unsigned)__cvta_generic_to_shared(p);
}
__device__ __forceinline__ void mma_f16(float* d, const unsigned* a, unsigned b0, unsigned b1) {
    asm volatile(
        "mma.sync.aligned.m16n8k16.row.col.f32.f16.f16.f32 "
        "{%0,%1,%2,%3}, {%4,%5,%6,%7}, {%8,%9}, {%0,%1,%2,%3};"
        : "+f"(d[0]), "+f"(d[1]), "+f"(d[2]), "+f"(d[3])
        : "r"(a[0]), "r"(a[1]), "r"(a[2]), "r"(a[3]), "r"(b0), "r"(b1));
}
__device__ __forceinline__ void ldsm4(unsigned* r, unsigned addr) {
    asm volatile("ldmatrix.sync.aligned.m8n8.x4.shared.b16 {%0,%1,%2,%3}, [%4];"
                 : "=r"(r[0]), "=r"(r[1]), "=r"(r[2]), "=r"(r[3]) : "r"(addr));
}
__device__ __forceinline__ void cp16(unsigned s, const void* g) {
    asm volatile("cp.async.ca.shared.global [%0], [%1], 16;" :: "r"(s), "l"(g));
}
__device__ __forceinline__ void red_v2(float* p, float a, float b) {
    asm volatile("red.global.add.v2.f32 [%0], {%1, %2};" :: "l"(p), "f"(a), "f"(b) : "memory");
}

// ---------------- kernel 1: reset scratch ----------------
__global__ void k_init() {
    int i = blockIdx.x * blockDim.x + threadIdx.x;
    for (; i < PERM_SZ; i += gridDim.x * blockDim.x) g_perm[i] = -1;
    if (blockIdx.x == 0 && threadIdx.x == 0) {
        g_meta[0] = 0; g_meta[1] = 0; g_meta[2] = 0; g_meta[3] = 0;
    }
}

// ---------------- kernel 2: count in-args ----------------
__global__ void k_count(const int* __restrict__ is_in) {
    int s = 0;
    for (int i = blockIdx.x * blockDim.x + threadIdx.x; i < N_ARGS;
         i += gridDim.x * blockDim.x)
        s += is_in[i];
    #pragma unroll
    for (int o = 16; o; o >>= 1) s += __shfl_down_sync(0xffffffffu, s, o);
    __shared__ int sh[8];
    if ((threadIdx.x & 31) == 0) sh[threadIdx.x >> 5] = s;
    __syncthreads();
    if (threadIdx.x < 8) {
        s = sh[threadIdx.x];
        #pragma unroll
        for (int o = 4; o; o >>= 1) s += __shfl_down_sync(0xffu, s, o);
        if (threadIdx.x == 0) atomicAdd(&g_meta[0], s);
    }
}

// ---------------- kernel 3: place args ----------------
__global__ void k_place(const int* __restrict__ is_in) {
    const int i = blockIdx.x * blockDim.x + threadIdx.x;
    const int pad = (g_meta[0] + TILE_M - 1) / TILE_M * TILE_M;
    const bool valid = (i < N_ARGS);
    const int v = valid ? is_in[i] : 0;
    const unsigned full = 0xffffffffu;
    const unsigned m_in  = __ballot_sync(full, valid && (v != 0));
    const unsigned m_out = __ballot_sync(full, valid && (v == 0));
    const int lane = threadIdx.x & 31;
    int b_in = 0, b_out = 0;
    if (lane == 0 && m_in)  b_in  = atomicAdd(&g_meta[1], __popc(m_in));
    if (lane == 0 && m_out) b_out = atomicAdd(&g_meta[2], __popc(m_out));
    b_in  = __shfl_sync(full, b_in, 0);
    b_out = __shfl_sync(full, b_out, 0);
    const unsigned lt = (1u << lane) - 1u;
    if (valid) {
        if (v) g_perm[b_in + __popc(m_in & lt)] = i;
        else   g_perm[pad + b_out + __popc(m_out & lt)] = i;
    }
}

// ---------------- kernel 4: pre-split W (fp16 hi/lo, x2048 pre-scale) ----------------
__global__ void k_prepW(const float* __restrict__ Win, const float* __restrict__ Wout) {
    const int i = blockIdx.x * blockDim.x + threadIdx.x;
    if (i >= KDIM * ROLE) return;
    const int k = i / ROLE, n = i % ROLE;
    const int chunk = k >> 6, kk = k & 63;
    const int pos = chunk * WCH + n * WSTRIDE + kk;

    float a = Win[i] * WSCALE;
    __half h = __float2half_rn(a);
    __half l = __float2half_rn(a - __half2float(h));
    g_WhIn[pos] = __half_as_ushort(h);
    g_WlIn[pos] = __half_as_ushort(l);

    a = Wout[i] * WSCALE;
    h = __float2half_rn(a);
    l = __float2half_rn(a - __half2float(h));
    g_WhOut[pos] = __half_as_ushort(h);
    g_WlOut[pos] = __half_as_ushort(l);
}

// ---------------- kernel 5: output init ----------------
__global__ void k_outinit(const float* __restrict__ ent,
                          const int* __restrict__ trig_ent,
                          float* __restrict__ out) {
    const int total = N_TRIG * (OUTW / 4);
    for (int idx = blockIdx.x * blockDim.x + threadIdx.x; idx < total;
         idx += gridDim.x * blockDim.x) {
        const int t  = idx / (OUTW / 4);
        const int c4 = (idx % (OUTW / 4)) * 4;
        float4 v = make_float4(0.f, 0.f, 0.f, 0.f);
        if (c4 < ENT_DIM)
            v = *(const float4*)(ent + (size_t)trig_ent[t] * ENT_DIM + c4);
        *(float4*)(out + (size_t)t * OUTW + c4) = v;
    }
}

// ---------------- kernel 6: HMMA fp16 2-pass, LDSM fragments, m32n64 warp tiles ----------------
__global__ void __launch_bounds__(THREADS, 1)
k_gemm_mma(const float* __restrict__ ent, const float* __restrict__ rel,
           const float* __restrict__ rtab, const int* __restrict__ rtype_ids,
           const int* __restrict__ arg_trig, const int* __restrict__ arg_rel,
           const int* __restrict__ arg_ent, float* __restrict__ out) {
    extern __shared__ char sm[];
    __shared__ int s_rel[TILE_M], s_rt[TILE_M], s_ent[TILE_M], s_trig[TILE_M], s_valid[TILE_M];

    const int tid  = threadIdx.x;
    const int wid  = tid >> 5;
    const int lane = tid & 31;
    const int g    = lane >> 2;
    const int tig  = lane & 3;
    const int wm   = wid & 3;        // m tile: rows [wm*32, wm*32+32)
    const int wn   = wid >> 2;       // n tile: cols [wn*64, wn*64+64)

    const unsigned sbase = sptr(sm);

    const int base = blockIdx.x * TILE_M;
    if (tid < TILE_M) {
        const int pa = g_perm[base + tid];
        s_valid[tid] = pa;
        if (pa >= 0) {
            const int r = arg_rel[pa];
            s_rel[tid]  = r;
            s_rt[tid]   = rtype_ids[r];
            s_ent[tid]  = arg_ent[pa];
            s_trig[tid] = arg_trig[pa];
        }
    }
    __syncthreads();

    const int pad = (g_meta[0] + TILE_M - 1) / TILE_M * TILE_M;
    const unsigned short* __restrict__ wh = (base < pad) ? g_WhIn : g_WhOut;
    const unsigned short* __restrict__ wl = (base < pad) ? g_WlIn : g_WlOut;

    char* A_s = sm;                       // single fp16 A tile

    auto prefetchW = [&](int c, int b) {
        char* dh = sm + OFF_W + b * WBUF_B;
        char* dl = dh + B_BYTES;
        const char* gh = (const char*)(wh + c * WCH);
        const char* gl = (const char*)(wl + c * WCH);
        #pragma unroll
        for (int j = 0; j < 5; j++) {
            const int idx = tid + j * THREADS;
            if (idx < B_BYTES / 16) {
                cp16(sptr(dh + idx * 16), gh + idx * 16);
                cp16(sptr(dl + idx * 16), gl + idx * 16);
            }
        }
        asm volatile("cp.async.commit_group;" ::: "memory");
    };

    // accumulators: [msub][nt][4]
    float D[2][8][4];
    #pragma unroll
    for (int ms = 0; ms < 2; ms++)
        #pragma unroll
        for (int t = 0; t < 8; t++) {
            D[ms][t][0] = 0.f; D[ms][t][1] = 0.f; D[ms][t][2] = 0.f; D[ms][t][3] = 0.f;
        }

    // ldmatrix lane offsets
    const unsigned a_lane = (unsigned)(((lane & 7) + ((lane >> 3) & 1) * 8) * ROWB
                                       + ((lane >> 4) & 1) * 16);
    const unsigned a_off0 = (unsigned)(wm * 32 * ROWB) + a_lane;
    const unsigned a_off1 = a_off0 + 16 * ROWB;
    const unsigned b_lane = (unsigned)((lane & 7) * ROWB + ((lane >> 3) & 1) * 16
                                       + ((lane >> 4) & 1) * 8 * ROWB);
    const unsigned b_off  = (unsigned)(wn * 64 * ROWB) + b_lane;

    prefetchW(0, 0);

    for (int c = 0; c < NCHUNK; c++) {
        const int b = c & 1;
        if (c + 1 < NCHUNK) prefetchW(c + 1, (c + 1) & 1);

        // ---- gather X chunk, convert fp16, store to A smem ----
        {
            const int ck = c * KC;
            #pragma unroll
            for (int j = 0; j < 4; j++) {
                const int idx = tid + j * THREADS;
                const int row = idx >> 4;
                const int gq  = idx & 15;
                const int k0  = ck + gq * 4;
                float4 v = make_float4(0.f, 0.f, 0.f, 0.f);
                if (s_valid[row] >= 0) {
                    if (k0 < REL_R)
                        v = *(const float4*)(rel + (size_t)s_rel[row] * REL_R + k0);
                    else if (k0 < REL_R + RTYPE_D)
                        v = *(const float4*)(rtab + (size_t)s_rt[row] * RTYPE_D + (k0 - REL_R));
                    else
                        v = *(const float4*)(ent + (size_t)s_ent[row] * ENT_DIM + (k0 - REL_R - RTYPE_D));
                }
                unsigned u0, u1;
                {
                    __half2 p0 = __floats2half2_rn(v.x, v.y);
                    __half2 p1 = __floats2half2_rn(v.z, v.w);
                    u0 = *(unsigned*)&p0;
                    u1 = *(unsigned*)&p1;
                }
                uint2 uu; uu.x = u0; uu.y = u1;
                *(uint2*)(A_s + row * ROWB + gq * 8) = uu;
            }
        }

        if (c + 1 < NCHUNK)
            asm volatile("cp.async.wait_group 1;" ::: "memory");
        else
            asm volatile("cp.async.wait_group 0;" ::: "memory");
        __syncthreads();

        const unsigned sA  = sbase;
        const unsigned sBh = sbase + OFF_W + b * WBUF_B;
        const unsigned sBl = sBh + B_BYTES;

        #pragma unroll
        for (int ks = 0; ks < 4; ks++) {
            const unsigned ko = (unsigned)(ks * 32);
            unsigned a[8], bh[16], bl[16];
            ldsm4(a,     sA + a_off0 + ko);
            ldsm4(a + 4, sA + a_off1 + ko);
            #pragma unroll
            for (int p = 0; p < 4; p++) {
                ldsm4(bh + p * 4, sBh + b_off + (unsigned)(p * 16 * ROWB) + ko);
                ldsm4(bl + p * 4, sBl + b_off + (unsigned)(p * 16 * ROWB) + ko);
            }
            #pragma unroll
            for (int ms = 0; ms < 2; ms++) {
                const unsigned* aF = a + ms * 4;
                #pragma unroll
                for (int nt = 0; nt < 8; nt++) {
                    const int bi = (nt >> 1) * 4 + (nt & 1) * 2;
                    mma_f16(D[ms][nt], aF, bh[bi], bh[bi + 1]);   // X * Wh
                    mma_f16(D[ms][nt], aF, bl[bi], bl[bi + 1]);   // X * Wl
                }
            }
        }
        __syncthreads();
    }

    // ---- epilogue: unscale (1/2048) and scatter via v2 atomics ----
    #pragma unroll
    for (int ms = 0; ms < 2; ms++) {
        #pragma unroll
        for (int half = 0; half < 2; half++) {
            const int row = wm * 32 + ms * 16 + g + half * 8;
            if (s_valid[row] < 0) continue;
            float* p = out + (size_t)s_trig[row] * OUTW + ENT_DIM + wn * 64 + tig * 2;
            #pragma unroll
            for (int nt = 0; nt < 8; nt++)
                red_v2(p + nt * 8,
                       D[ms][nt][half * 2]     * INV_SCALE,
                       D[ms][nt][half * 2 + 1] * INV_SCALE);
        }
    }
}

extern "C" void kernel_launch(void* const* d_in, const int* in_sizes, int n_in,
                              void* d_out, int out_size) {
    const float* ent       = (const float*)d_in[0];
    const float* rel       = (const float*)d_in[1];
    const float* rtab      = (const float*)d_in[2];
    const float* Win       = (const float*)d_in[3];
    const float* Wout      = (const float*)d_in[4];
    const int*   rtype_ids = (const int*)d_in[5];
    const int*   trig_ent  = (const int*)d_in[6];
    const int*   arg_trig  = (const int*)d_in[7];
    const int*   arg_rel   = (const int*)d_in[8];
    const int*   arg_ent   = (const int*)d_in[9];
    const int*   arg_is_in = (const int*)d_in[10];
    float* out = (float*)d_out;

    cudaFuncSetAttribute(k_gemm_mma, cudaFuncAttributeMaxDynamicSharedMemorySize, SMEM_DYN);

    k_init<<<256, 256>>>();
    k_count<<<128, 256>>>(arg_is_in);
    k_place<<<(N_ARGS + 255) / 256, 256>>>(arg_is_in);
    k_prepW<<<(KDIM * ROLE + 255) / 256, 256>>>(Win, Wout);
    k_outinit<<<1024, 256>>>(ent, trig_ent, out);
    k_gemm_mma<<<NT, THREADS, SMEM_DYN>>>(ent, rel, rtab, rtype_ids,
                                          arg_trig, arg_rel, arg_ent, out);
}